// round 13
// baseline (speedup 1.0000x reference)
#include <cuda_runtime.h>
#include <cuda_fp16.h>
#include <mma.h>
using namespace nvcuda;

// Problem constants (fixed by the dataset)
#define N_NODES 50000
#define NE      800000
#define IN_DIM  64
#define HID     128
#define HEADS   4
#define NCLS    2

// ---------------- scratch: EXACT layout of the passing Round-9/10/11 kernel ----------------
__device__ __half g_A[N_NODES * HEADS * HID];   // 51.2MB
__device__ __half g_B[N_NODES * HEADS * HID];   // 51.2MB
__device__ float  g_agg[N_NODES * HEADS * IN_DIM]; // 51.2MB
__device__ float  g_h0[N_NODES * HID];          // 25.6MB
__device__ float  g_h1[N_NODES * HID];          // 25.6MB (repurposed: fp16 x copy)
__device__ int    g_cnt[N_NODES];
__device__ int    g_off[N_NODES + 1];
__device__ int    g_cur[N_NODES];
__device__ int    g_scol[NE];
__device__ int    g_ei32[2 * NE];
__device__ float  g_S[HEADS];
__device__ int    g_is64;

__device__ __forceinline__ float tanh_fast(float v) {
    float r;
    asm("tanh.approx.f32 %0, %1;" : "=f"(r) : "f"(v));
    return r;
}

// ---------------- K0a: detect edge_index dtype (int64 vs int32) ----------------
__global__ void k_detect(const int* __restrict__ ei32) {
    __shared__ int any;
    if (threadIdx.x == 0) any = 0;
    __syncthreads();
    for (int i = threadIdx.x; i < 1024; i += blockDim.x) {
        if (ei32[2 * i + 1] != 0) any = 1;
    }
    __syncthreads();
    if (threadIdx.x == 0) g_is64 = (any == 0) ? 1 : 0;
}

// ---------------- convert + histogram fused ----------------
__global__ void k_convert_hist(const void* __restrict__ ei) {
    int e = blockIdx.x * blockDim.x + threadIdx.x;
    if (e < 2 * NE) {
        int v;
        if (g_is64) v = (int)((const long long*)ei)[e];
        else        v = ((const int*)ei)[e];
        g_ei32[e] = v;
        if (e < NE) atomicAdd(&g_cnt[v], 1);
    }
}

__global__ void k_zero() {
    int i = blockIdx.x * blockDim.x + threadIdx.x;
    if (i < N_NODES) g_cnt[i] = 0;
    if (i < HEADS) g_S[i] = 0.f;
}

// ---------------- fp16 copy of x into (dead) g_h1 storage ----------------
__global__ void k_x16(const float* __restrict__ x) {
    int i = blockIdx.x * blockDim.x + threadIdx.x;
    if (i < N_NODES * IN_DIM) ((__half*)g_h1)[i] = __float2half(x[i]);
}

// ---------------- K1: A/B tables via wmma (unchanged) ----------------
#define XS_LD 72
#define WS_LD 136
#define ST_LD 132
#define SMB   (128 * XS_LD * 2 + 64 * WS_LD * 2)   // 35840 bytes

__global__ __launch_bounds__(256) void k_ab_mma(
    const float* __restrict__ x, const float* __restrict__ w1, const float* __restrict__ b1)
{
    __shared__ __align__(16) char sm[SMB];
    __half* Xs = (__half*)sm;
    __half* Ws = (__half*)(sm + 128 * XS_LD * 2);
    float*  St = (float*)sm;

    int t = threadIdx.x;
    int warp = t >> 5;
    int n0 = blockIdx.x * 128;
    int part = blockIdx.y;
    int head = part & 3;
    bool isA = part < 4;
    int krow0 = isA ? 0 : IN_DIM;

#pragma unroll
    for (int i = 0; i < 8; i++) {
        int id = t + i * 256;
        int r = id >> 4;
        int c4 = (id & 15) * 4;
        int n = n0 + r;
        float4 v = make_float4(0.f, 0.f, 0.f, 0.f);
        if (n < N_NODES) v = *(const float4*)(x + (size_t)n * IN_DIM + c4);
        *(__half2*)(Xs + r * XS_LD + c4)     = __floats2half2_rn(v.x, v.y);
        *(__half2*)(Xs + r * XS_LD + c4 + 2) = __floats2half2_rn(v.z, v.w);
    }
#pragma unroll
    for (int i = 0; i < 8; i++) {
        int id = t + i * 256;
        int kr = id >> 5;
        int d4 = (id & 31) * 4;
        float4 v = *(const float4*)(w1 + head * (2 * IN_DIM * HID) + (size_t)(krow0 + kr) * HID + d4);
        *(__half2*)(Ws + kr * WS_LD + d4)     = __floats2half2_rn(v.x, v.y);
        *(__half2*)(Ws + kr * WS_LD + d4 + 2) = __floats2half2_rn(v.z, v.w);
    }
    __syncthreads();

    int m0w = (warp >> 1) * 32;
    int n0w = (warp & 1) * 64;

    wmma::fragment<wmma::accumulator, 16, 16, 16, float> acc[2][4];
#pragma unroll
    for (int mi = 0; mi < 2; mi++)
#pragma unroll
        for (int ni = 0; ni < 4; ni++) wmma::fill_fragment(acc[mi][ni], 0.f);

#pragma unroll
    for (int kk = 0; kk < 4; kk++) {
        wmma::fragment<wmma::matrix_a, 16, 16, 16, __half, wmma::row_major> af[2];
        wmma::fragment<wmma::matrix_b, 16, 16, 16, __half, wmma::row_major> bf[4];
#pragma unroll
        for (int mi = 0; mi < 2; mi++)
            wmma::load_matrix_sync(af[mi], Xs + (m0w + mi * 16) * XS_LD + kk * 16, XS_LD);
#pragma unroll
        for (int ni = 0; ni < 4; ni++)
            wmma::load_matrix_sync(bf[ni], Ws + (kk * 16) * WS_LD + n0w + ni * 16, WS_LD);
#pragma unroll
        for (int mi = 0; mi < 2; mi++)
#pragma unroll
            for (int ni = 0; ni < 4; ni++)
                wmma::mma_sync(acc[mi][ni], af[mi], bf[ni], acc[mi][ni]);
    }

    __half* dst = isA ? g_A : g_B;
#pragma unroll
    for (int hh = 0; hh < 2; hh++) {
        __syncthreads();
        if ((warp >> 2) == hh) {
#pragma unroll
            for (int mi = 0; mi < 2; mi++)
#pragma unroll
                for (int ni = 0; ni < 4; ni++)
                    wmma::store_matrix_sync(St + (m0w - hh * 64 + mi * 16) * ST_LD + n0w + ni * 16,
                                            acc[mi][ni], ST_LD, wmma::mem_row_major);
        }
        __syncthreads();
#pragma unroll
        for (int i = 0; i < 16; i++) {
            int id = t + i * 256;
            int r = id >> 6, pc = id & 63;
            int n = n0 + hh * 64 + r;
            if (n >= N_NODES) continue;
            int d = 2 * pc;
            float v0 = St[r * ST_LD + d];
            float v1 = St[r * ST_LD + d + 1];
            if (isA) {
                v0 += b1[head * HID + d];
                v1 += b1[head * HID + d + 1];
            }
            *(__half2*)(dst + (size_t)n * (HEADS * HID) + head * HID + d) = __floats2half2_rn(v0, v1);
        }
    }
}

// ---------------- scan (verbatim) ----------------
__global__ __launch_bounds__(1024) void k_scan() {
    __shared__ int wsum[32];
    __shared__ int carry;
    int t = threadIdx.x, lane = t & 31, wid = t >> 5;
    if (t == 0) carry = 0;
    __syncthreads();
    for (int base = 0; base < N_NODES; base += 1024) {
        int i = base + t;
        int v = (i < N_NODES) ? g_cnt[i] : 0;
        int s = v;
#pragma unroll
        for (int o = 1; o < 32; o <<= 1) {
            int u = __shfl_up_sync(0xffffffffu, s, o);
            if (lane >= o) s += u;
        }
        if (lane == 31) wsum[wid] = s;
        __syncthreads();
        if (wid == 0) {
            int ws = wsum[lane];
#pragma unroll
            for (int o = 1; o < 32; o <<= 1) {
                int u = __shfl_up_sync(0xffffffffu, ws, o);
                if (lane >= o) ws += u;
            }
            wsum[lane] = ws;
        }
        __syncthreads();
        int incl = s + ((wid > 0) ? wsum[wid - 1] : 0) + carry;
        if (i < N_NODES) {
            int ex = incl - v;
            g_off[i] = ex;
            g_cur[i] = ex;
        }
        __syncthreads();
        if (t == 1023) carry = incl;
        __syncthreads();
    }
    if (t == 0) g_off[N_NODES] = carry;
}

__global__ void k_scatter() {
    int e = blockIdx.x * blockDim.x + threadIdx.x;
    if (e < NE) {
        int r = g_ei32[e];
        int c = g_ei32[NE + e];
        int p = atomicAdd(&g_cur[r], 1);
        g_scol[p] = c;
    }
}

// ---------------- fused edge pass: 4 warps per node, 2 nodes per block ----------------
// fp16 x (from g_h1 alias), streaming hints to keep g_B resident in L2.
__global__ __launch_bounds__(256) void k_edge(const float* __restrict__ w2, const float* __restrict__ b2)
{
    __shared__ float s_acc[2][4][4][64];   // [slot][warpInNode][head][dim]
    __shared__ float s_sum[2][4][4];       // [slot][warpInNode][head]

    const __half* x16 = (const __half*)g_h1;

    int t = threadIdx.x;
    int slot = t >> 7;
    int win  = (t >> 5) & 3;
    int lane = t & 31;
    int node = blockIdx.x * 2 + slot;

    float a[4][4], w2l[4][4], eb2[4];
#pragma unroll
    for (int h = 0; h < 4; h++) {
        uint2 ar = *(const uint2*)(g_A + (size_t)node * 512 + h * 128 + lane * 4);
        float2 f0 = __half22float2(*(__half2*)&ar.x);
        float2 f1 = __half22float2(*(__half2*)&ar.y);
        a[h][0] = f0.x; a[h][1] = f0.y; a[h][2] = f1.x; a[h][3] = f1.y;
        float4 wv = *(const float4*)&w2[h * 128 + lane * 4];
        w2l[h][0] = wv.x; w2l[h][1] = wv.y; w2l[h][2] = wv.z; w2l[h][3] = wv.w;
        eb2[h] = __expf(b2[h]);
    }

    float acc[4][2];
#pragma unroll
    for (int h = 0; h < 4; h++) { acc[h][0] = 0.f; acc[h][1] = 0.f; }
    float ssum[4] = {0.f, 0.f, 0.f, 0.f};

    int beg = g_off[node], end = g_off[node + 1];
    int len = end - beg;
    int q = len >> 2, rmd = len & 3;
    int myBeg = beg + win * q + min(win, rmd);
    int myEnd = myBeg + q + (win < rmd ? 1 : 0);

    int i = myBeg;
    for (; i + 1 < myEnd; i += 2) {
        int c0 = __ldcs(&g_scol[i]);
        int c1 = __ldcs(&g_scol[i + 1]);
        uint2 br0[4], br1[4];
        const __half* bp0 = g_B + (size_t)c0 * 512 + lane * 4;
        const __half* bp1 = g_B + (size_t)c1 * 512 + lane * 4;
#pragma unroll
        for (int h = 0; h < 4; h++) br0[h] = *(const uint2*)(bp0 + h * 128);
#pragma unroll
        for (int h = 0; h < 4; h++) br1[h] = *(const uint2*)(bp1 + h * 128);
        float2 xv0 = __half22float2(*(const __half2*)(x16 + c0 * 64 + lane * 2));
        float2 xv1 = __half22float2(*(const __half2*)(x16 + c1 * 64 + lane * 2));

        float p0[4], p1[4];
#pragma unroll
        for (int h = 0; h < 4; h++) {
            float2 g0 = __half22float2(*(__half2*)&br0[h].x);
            float2 g1 = __half22float2(*(__half2*)&br0[h].y);
            float s = 0.f;
            s = fmaf(w2l[h][0], tanh_fast(a[h][0] + g0.x), s);
            s = fmaf(w2l[h][1], tanh_fast(a[h][1] + g0.y), s);
            s = fmaf(w2l[h][2], tanh_fast(a[h][2] + g1.x), s);
            s = fmaf(w2l[h][3], tanh_fast(a[h][3] + g1.y), s);
            p0[h] = s;
            float2 h0v = __half22float2(*(__half2*)&br1[h].x);
            float2 h1v = __half22float2(*(__half2*)&br1[h].y);
            float u = 0.f;
            u = fmaf(w2l[h][0], tanh_fast(a[h][0] + h0v.x), u);
            u = fmaf(w2l[h][1], tanh_fast(a[h][1] + h0v.y), u);
            u = fmaf(w2l[h][2], tanh_fast(a[h][2] + h1v.x), u);
            u = fmaf(w2l[h][3], tanh_fast(a[h][3] + h1v.y), u);
            p1[h] = u;
        }
#pragma unroll
        for (int o = 16; o; o >>= 1) {
            p0[0] += __shfl_xor_sync(0xffffffffu, p0[0], o);
            p0[1] += __shfl_xor_sync(0xffffffffu, p0[1], o);
            p0[2] += __shfl_xor_sync(0xffffffffu, p0[2], o);
            p0[3] += __shfl_xor_sync(0xffffffffu, p0[3], o);
            p1[0] += __shfl_xor_sync(0xffffffffu, p1[0], o);
            p1[1] += __shfl_xor_sync(0xffffffffu, p1[1], o);
            p1[2] += __shfl_xor_sync(0xffffffffu, p1[2], o);
            p1[3] += __shfl_xor_sync(0xffffffffu, p1[3], o);
        }
#pragma unroll
        for (int h = 0; h < 4; h++) {
            float e0 = __expf(p0[h]) * eb2[h];
            float e1 = __expf(p1[h]) * eb2[h];
            ssum[h] += e0 + e1;
            acc[h][0] = fmaf(e0, xv0.x, acc[h][0]);
            acc[h][1] = fmaf(e0, xv0.y, acc[h][1]);
            acc[h][0] = fmaf(e1, xv1.x, acc[h][0]);
            acc[h][1] = fmaf(e1, xv1.y, acc[h][1]);
        }
    }
    if (i < myEnd) {
        int c = __ldcs(&g_scol[i]);
        float part[4];
#pragma unroll
        for (int h = 0; h < 4; h++) {
            uint2 br = *(const uint2*)(g_B + (size_t)c * 512 + h * 128 + lane * 4);
            float2 g0 = __half22float2(*(__half2*)&br.x);
            float2 g1 = __half22float2(*(__half2*)&br.y);
            float s = 0.f;
            s = fmaf(w2l[h][0], tanh_fast(a[h][0] + g0.x), s);
            s = fmaf(w2l[h][1], tanh_fast(a[h][1] + g0.y), s);
            s = fmaf(w2l[h][2], tanh_fast(a[h][2] + g1.x), s);
            s = fmaf(w2l[h][3], tanh_fast(a[h][3] + g1.y), s);
            part[h] = s;
        }
#pragma unroll
        for (int o = 16; o; o >>= 1) {
            part[0] += __shfl_xor_sync(0xffffffffu, part[0], o);
            part[1] += __shfl_xor_sync(0xffffffffu, part[1], o);
            part[2] += __shfl_xor_sync(0xffffffffu, part[2], o);
            part[3] += __shfl_xor_sync(0xffffffffu, part[3], o);
        }
        float2 xv = __half22float2(*(const __half2*)(x16 + c * 64 + lane * 2));
#pragma unroll
        for (int h = 0; h < 4; h++) {
            float e = __expf(part[h]) * eb2[h];
            ssum[h] += e;
            acc[h][0] = fmaf(e, xv.x, acc[h][0]);
            acc[h][1] = fmaf(e, xv.y, acc[h][1]);
        }
    }

#pragma unroll
    for (int h = 0; h < 4; h++) {
        *(float2*)&s_acc[slot][win][h][lane * 2] = make_float2(acc[h][0], acc[h][1]);
    }
    if (lane == 0) {
#pragma unroll
        for (int h = 0; h < 4; h++) s_sum[slot][win][h] = ssum[h];
    }
    __syncthreads();

    for (int idx = t; idx < 512; idx += 256) {
        int sl = idx >> 8;
        int rest = idx & 255;
        int h = rest >> 6, d = rest & 63;
        int nn = blockIdx.x * 2 + sl;
        float v = s_acc[sl][0][h][d] + s_acc[sl][1][h][d]
                + s_acc[sl][2][h][d] + s_acc[sl][3][h][d];
        __stcs(&g_agg[(size_t)nn * 256 + h * 64 + d], v);   // streaming: don't evict g_B
    }
    if (t < 8) {
        int sl = t >> 2, h = t & 3;
        float v = s_sum[sl][0][h] + s_sum[sl][1][h] + s_sum[sl][2][h] + s_sum[sl][3][h];
        atomicAdd(&g_S[h], v);
    }
}

// ---------------- node GEMMs via wmma with power-of-2 scaling; L=1 fuses classifier ----
template <int KDIM, int L>
__global__ __launch_bounds__(256) void k_ngemm(
    const float* __restrict__ W, const float* __restrict__ bias,
    const float* __restrict__ bng, const float* __restrict__ bnb,
    const float* __restrict__ bnm, const float* __restrict__ bnv,
    const float* __restrict__ clw, const float* __restrict__ clb,
    float* __restrict__ out)
{
    __shared__ __align__(16) char sm[SMB];
    __half* Xs = (__half*)sm;
    __half* Ws = (__half*)(sm + 128 * XS_LD * 2);
    float*  St = (float*)sm;
    __shared__ float sinv[4];
    __shared__ float Wc[256];

    constexpr float UPSCALE   = (L == 0) ? 65536.f : 262144.f;
    constexpr float DOWNSCALE = 1.f / UPSCALE;

    const float* Ag = (L == 0) ? g_agg : g_h0;
    float* Og = g_h0;

    int t = threadIdx.x;
    int warp = t >> 5;
    int n0 = blockIdx.x * 128;
    if (L == 0) {
        if (t < 4) sinv[t] = UPSCALE / g_S[t];
        __syncthreads();
    } else {
        Wc[t] = clw[t];
        __syncthreads();
    }

    int m0w = (warp >> 1) * 32;
    int n0w = (warp & 1) * 64;

    wmma::fragment<wmma::accumulator, 16, 16, 16, float> acc[2][4];
#pragma unroll
    for (int mi = 0; mi < 2; mi++)
#pragma unroll
        for (int ni = 0; ni < 4; ni++) wmma::fill_fragment(acc[mi][ni], 0.f);

    for (int kc = 0; kc < KDIM; kc += 64) {
        __syncthreads();
#pragma unroll
        for (int i = 0; i < 8; i++) {
            int id = t + i * 256;
            int r = id >> 4;
            int c4 = (id & 15) * 4;
            int n = n0 + r;
            float4 v = make_float4(0.f, 0.f, 0.f, 0.f);
            if (n < N_NODES) v = *(const float4*)(Ag + (size_t)n * KDIM + kc + c4);
            float s = (L == 0) ? sinv[(kc + c4) >> 6] : UPSCALE;
            v.x *= s; v.y *= s; v.z *= s; v.w *= s;
            *(__half2*)(Xs + r * XS_LD + c4)     = __floats2half2_rn(v.x, v.y);
            *(__half2*)(Xs + r * XS_LD + c4 + 2) = __floats2half2_rn(v.z, v.w);
        }
#pragma unroll
        for (int i = 0; i < 8; i++) {
            int id = t + i * 256;
            int kr = id >> 5;
            int d4 = (id & 31) * 4;
            float4 v = *(const float4*)(W + (size_t)(kc + kr) * HID + d4);
            *(__half2*)(Ws + kr * WS_LD + d4)     = __floats2half2_rn(v.x, v.y);
            *(__half2*)(Ws + kr * WS_LD + d4 + 2) = __floats2half2_rn(v.z, v.w);
        }
        __syncthreads();
#pragma unroll
        for (int kk = 0; kk < 4; kk++) {
            wmma::fragment<wmma::matrix_a, 16, 16, 16, __half, wmma::row_major> af[2];
            wmma::fragment<wmma::matrix_b, 16, 16, 16, __half, wmma::row_major> bf[4];
#pragma unroll
            for (int mi = 0; mi < 2; mi++)
                wmma::load_matrix_sync(af[mi], Xs + (m0w + mi * 16) * XS_LD + kk * 16, XS_LD);
#pragma unroll
            for (int ni = 0; ni < 4; ni++)
                wmma::load_matrix_sync(bf[ni], Ws + (kk * 16) * WS_LD + n0w + ni * 16, WS_LD);
#pragma unroll
            for (int mi = 0; mi < 2; mi++)
#pragma unroll
                for (int ni = 0; ni < 4; ni++)
                    wmma::mma_sync(acc[mi][ni], af[mi], bf[ni], acc[mi][ni]);
        }
    }

#pragma unroll
    for (int hh = 0; hh < 2; hh++) {
        __syncthreads();
        if ((warp >> 2) == hh) {
#pragma unroll
            for (int mi = 0; mi < 2; mi++)
#pragma unroll
                for (int ni = 0; ni < 4; ni++)
                    wmma::store_matrix_sync(St + (m0w - hh * 64 + mi * 16) * ST_LD + n0w + ni * 16,
                                            acc[mi][ni], ST_LD, wmma::mem_row_major);
        }
        __syncthreads();
#pragma unroll
        for (int i = 0; i < 16; i++) {
            int id = t + i * 256;
            int r = id >> 6, pc = id & 63;
            int n = n0 + hh * 64 + r;
            if (n >= N_NODES) continue;
            int d = 2 * pc;
            float v0 = St[r * ST_LD + d]     * DOWNSCALE + bias[d];
            float v1 = St[r * ST_LD + d + 1] * DOWNSCALE + bias[d + 1];
            float g0 = bng[L * 128 + d]     * rsqrtf(bnv[L * 128 + d]     + 1e-5f);
            float g1 = bng[L * 128 + d + 1] * rsqrtf(bnv[L * 128 + d + 1] + 1e-5f);
            v0 = (v0 - bnm[L * 128 + d])     * g0 + bnb[L * 128 + d];
            v1 = (v1 - bnm[L * 128 + d + 1]) * g1 + bnb[L * 128 + d + 1];
            v0 = fmaxf(v0, 0.f);
            v1 = fmaxf(v1, 0.f);
            if (L == 0) {
                *(float2*)(Og + (size_t)n * HID + d) = make_float2(v0, v1);
            } else {
                St[r * ST_LD + d]     = v0;
                St[r * ST_LD + d + 1] = v1;
            }
        }
        if (L == 1) {
            __syncthreads();
            int r = t >> 2, qq = t & 3;
            int n = n0 + hh * 64 + r;
            float c0 = 0.f, c1 = 0.f;
            int k0 = qq * 32;
#pragma unroll
            for (int k = 0; k < 32; k++) {
                float v = St[r * ST_LD + k0 + k];
                c0 = fmaf(v, Wc[(k0 + k) * 2], c0);
                c1 = fmaf(v, Wc[(k0 + k) * 2 + 1], c1);
            }
            c0 += __shfl_xor_sync(0xffffffffu, c0, 1);
            c0 += __shfl_xor_sync(0xffffffffu, c0, 2);
            c1 += __shfl_xor_sync(0xffffffffu, c1, 1);
            c1 += __shfl_xor_sync(0xffffffffu, c1, 2);
            if (qq == 0 && n < N_NODES) {
                out[n * 2]     = c0 + clb[0];
                out[n * 2 + 1] = c1 + clb[1];
            }
        }
    }
}

// ---------------- launch ----------------
extern "C" void kernel_launch(void* const* d_in, const int* in_sizes, int n_in,
                              void* d_out, int out_size)
{
    const float* x   = (const float*)d_in[0];
    const void*  ei  = d_in[1];
    const float* w1  = (const float*)d_in[2];
    const float* b1  = (const float*)d_in[3];
    const float* w2  = (const float*)d_in[4];
    const float* b2  = (const float*)d_in[5];
    const float* cw0 = (const float*)d_in[6];
    const float* cb0 = (const float*)d_in[7];
    const float* cw1 = (const float*)d_in[8];
    const float* cb1 = (const float*)d_in[9];
    const float* bng = (const float*)d_in[10];
    const float* bnb = (const float*)d_in[11];
    const float* bnm = (const float*)d_in[12];
    const float* bnv = (const float*)d_in[13];
    const float* clw = (const float*)d_in[14];
    const float* clb = (const float*)d_in[15];
    float*       out = (float*)d_out;

    int nblk128 = (N_NODES + 127) / 128;

    k_zero<<<(N_NODES + 255) / 256, 256>>>();
    k_detect<<<1, 256>>>((const int*)ei);
    k_convert_hist<<<(2 * NE + 255) / 256, 256>>>(ei);

    k_ab_mma<<<dim3(nblk128, 8), 256>>>(x, w1, b1);

    k_x16<<<(N_NODES * IN_DIM + 255) / 256, 256>>>(x);
    k_scan<<<1, 1024>>>();
    k_scatter<<<(NE + 255) / 256, 256>>>();
    k_edge<<<N_NODES / 2, 256>>>(w2, b2);

    k_ngemm<256, 0><<<nblk128, 256>>>(cw0, cb0, bng, bnb, bnm, bnv, nullptr, nullptr, nullptr);
    k_ngemm<128, 1><<<nblk128, 256>>>(cw1, cb1, bng, bnb, bnm, bnv, clw, clb, out);
}

// round 15
// speedup vs baseline: 1.3022x; 1.3022x over previous
#include <cuda_runtime.h>
#include <cuda_fp16.h>
#include <cstdint>
#include <mma.h>
using namespace nvcuda;

// Problem constants (fixed by the dataset)
#define N_NODES 50000
#define NE      800000
#define IN_DIM  64
#define HID     128
#define HEADS   4
#define NCLS    2

// ---------------- scratch: EXACT layout of the passing Round-9..11 kernel ----------------
__device__ __half g_A[N_NODES * HEADS * HID];   // 51.2MB
__device__ __half g_B[N_NODES * HEADS * HID];   // 51.2MB
__device__ float  g_agg[N_NODES * HEADS * IN_DIM]; // 51.2MB
__device__ float  g_h0[N_NODES * HID];          // 25.6MB
__device__ float  g_h1[N_NODES * HID];          // 25.6MB (unused; kept for layout pedigree)
__device__ int    g_cnt[N_NODES];
__device__ int    g_off[N_NODES + 1];
__device__ int    g_cur[N_NODES];
__device__ int    g_scol[NE];
__device__ int    g_ei32[2 * NE];
__device__ float  g_S[HEADS];
__device__ int    g_is64;

__device__ __forceinline__ unsigned h2tanh(unsigned v) {
    unsigned r;
    asm("tanh.approx.f16x2 %0, %1;" : "=r"(r) : "r"(v));
    return r;
}

__device__ __forceinline__ unsigned h2add(unsigned a, unsigned b) {
    __half2 r = __hadd2(*(__half2*)&a, *(__half2*)&b);
    return *(unsigned*)&r;
}

__device__ __forceinline__ float2 h2f2(unsigned v) {
    return __half22float2(*(__half2*)&v);
}

// ---------------- K0a: detect edge_index dtype (int64 vs int32) ----------------
__global__ void k_detect(const int* __restrict__ ei32) {
    __shared__ int any;
    if (threadIdx.x == 0) any = 0;
    __syncthreads();
    for (int i = threadIdx.x; i < 1024; i += blockDim.x) {
        if (ei32[2 * i + 1] != 0) any = 1;
    }
    __syncthreads();
    if (threadIdx.x == 0) g_is64 = (any == 0) ? 1 : 0;
}

// ---------------- convert + histogram fused ----------------
__global__ void k_convert_hist(const void* __restrict__ ei) {
    int e = blockIdx.x * blockDim.x + threadIdx.x;
    if (e < 2 * NE) {
        int v;
        if (g_is64) v = (int)((const long long*)ei)[e];
        else        v = ((const int*)ei)[e];
        g_ei32[e] = v;
        if (e < NE) atomicAdd(&g_cnt[v], 1);
    }
}

__global__ void k_zero() {
    int i = blockIdx.x * blockDim.x + threadIdx.x;
    if (i < N_NODES) g_cnt[i] = 0;
    if (i < HEADS) g_S[i] = 0.f;
}

// ---------------- K1: A/B tables via wmma (unchanged) ----------------
#define XS_LD 72
#define WS_LD 136
#define ST_LD 132
#define SMB   (128 * XS_LD * 2 + 64 * WS_LD * 2)   // 35840 bytes

__global__ __launch_bounds__(256) void k_ab_mma(
    const float* __restrict__ x, const float* __restrict__ w1, const float* __restrict__ b1)
{
    __shared__ __align__(16) char sm[SMB];
    __half* Xs = (__half*)sm;
    __half* Ws = (__half*)(sm + 128 * XS_LD * 2);
    float*  St = (float*)sm;

    int t = threadIdx.x;
    int warp = t >> 5;
    int n0 = blockIdx.x * 128;
    int part = blockIdx.y;
    int head = part & 3;
    bool isA = part < 4;
    int krow0 = isA ? 0 : IN_DIM;

#pragma unroll
    for (int i = 0; i < 8; i++) {
        int id = t + i * 256;
        int r = id >> 4;
        int c4 = (id & 15) * 4;
        int n = n0 + r;
        float4 v = make_float4(0.f, 0.f, 0.f, 0.f);
        if (n < N_NODES) v = *(const float4*)(x + (size_t)n * IN_DIM + c4);
        *(__half2*)(Xs + r * XS_LD + c4)     = __floats2half2_rn(v.x, v.y);
        *(__half2*)(Xs + r * XS_LD + c4 + 2) = __floats2half2_rn(v.z, v.w);
    }
#pragma unroll
    for (int i = 0; i < 8; i++) {
        int id = t + i * 256;
        int kr = id >> 5;
        int d4 = (id & 31) * 4;
        float4 v = *(const float4*)(w1 + head * (2 * IN_DIM * HID) + (size_t)(krow0 + kr) * HID + d4);
        *(__half2*)(Ws + kr * WS_LD + d4)     = __floats2half2_rn(v.x, v.y);
        *(__half2*)(Ws + kr * WS_LD + d4 + 2) = __floats2half2_rn(v.z, v.w);
    }
    __syncthreads();

    int m0w = (warp >> 1) * 32;
    int n0w = (warp & 1) * 64;

    wmma::fragment<wmma::accumulator, 16, 16, 16, float> acc[2][4];
#pragma unroll
    for (int mi = 0; mi < 2; mi++)
#pragma unroll
        for (int ni = 0; ni < 4; ni++) wmma::fill_fragment(acc[mi][ni], 0.f);

#pragma unroll
    for (int kk = 0; kk < 4; kk++) {
        wmma::fragment<wmma::matrix_a, 16, 16, 16, __half, wmma::row_major> af[2];
        wmma::fragment<wmma::matrix_b, 16, 16, 16, __half, wmma::row_major> bf[4];
#pragma unroll
        for (int mi = 0; mi < 2; mi++)
            wmma::load_matrix_sync(af[mi], Xs + (m0w + mi * 16) * XS_LD + kk * 16, XS_LD);
#pragma unroll
        for (int ni = 0; ni < 4; ni++)
            wmma::load_matrix_sync(bf[ni], Ws + (kk * 16) * WS_LD + n0w + ni * 16, WS_LD);
#pragma unroll
        for (int mi = 0; mi < 2; mi++)
#pragma unroll
            for (int ni = 0; ni < 4; ni++)
                wmma::mma_sync(acc[mi][ni], af[mi], bf[ni], acc[mi][ni]);
    }

    __half* dst = isA ? g_A : g_B;
#pragma unroll
    for (int hh = 0; hh < 2; hh++) {
        __syncthreads();
        if ((warp >> 2) == hh) {
#pragma unroll
            for (int mi = 0; mi < 2; mi++)
#pragma unroll
                for (int ni = 0; ni < 4; ni++)
                    wmma::store_matrix_sync(St + (m0w - hh * 64 + mi * 16) * ST_LD + n0w + ni * 16,
                                            acc[mi][ni], ST_LD, wmma::mem_row_major);
        }
        __syncthreads();
#pragma unroll
        for (int i = 0; i < 16; i++) {
            int id = t + i * 256;
            int r = id >> 6, pc = id & 63;
            int n = n0 + hh * 64 + r;
            if (n >= N_NODES) continue;
            int d = 2 * pc;
            float v0 = St[r * ST_LD + d];
            float v1 = St[r * ST_LD + d + 1];
            if (isA) {
                v0 += b1[head * HID + d];
                v1 += b1[head * HID + d + 1];
            }
            *(__half2*)(dst + (size_t)n * (HEADS * HID) + head * HID + d) = __floats2half2_rn(v0, v1);
        }
    }
}

// ---------------- scan (verbatim) ----------------
__global__ __launch_bounds__(1024) void k_scan() {
    __shared__ int wsum[32];
    __shared__ int carry;
    int t = threadIdx.x, lane = t & 31, wid = t >> 5;
    if (t == 0) carry = 0;
    __syncthreads();
    for (int base = 0; base < N_NODES; base += 1024) {
        int i = base + t;
        int v = (i < N_NODES) ? g_cnt[i] : 0;
        int s = v;
#pragma unroll
        for (int o = 1; o < 32; o <<= 1) {
            int u = __shfl_up_sync(0xffffffffu, s, o);
            if (lane >= o) s += u;
        }
        if (lane == 31) wsum[wid] = s;
        __syncthreads();
        if (wid == 0) {
            int ws = wsum[lane];
#pragma unroll
            for (int o = 1; o < 32; o <<= 1) {
                int u = __shfl_up_sync(0xffffffffu, ws, o);
                if (lane >= o) ws += u;
            }
            wsum[lane] = ws;
        }
        __syncthreads();
        int incl = s + ((wid > 0) ? wsum[wid - 1] : 0) + carry;
        if (i < N_NODES) {
            int ex = incl - v;
            g_off[i] = ex;
            g_cur[i] = ex;
        }
        __syncthreads();
        if (t == 1023) carry = incl;
        __syncthreads();
    }
    if (t == 0) g_off[N_NODES] = carry;
}

__global__ void k_scatter() {
    int e = blockIdx.x * blockDim.x + threadIdx.x;
    if (e < NE) {
        int r = g_ei32[e];
        int c = g_ei32[NE + e];
        int p = atomicAdd(&g_cur[r], 1);
        g_scol[p] = c;
    }
}

// ---------------- fused edge pass: 4 warps per node, 2 nodes per block ----------------
// tanh via MUFU f16x2 (half the MUFU ops); score/softmax/agg stay fp32.
__global__ __launch_bounds__(256) void k_edge(
    const float* __restrict__ x, const float* __restrict__ w2, const float* __restrict__ b2)
{
    __shared__ float s_acc[2][4][4][64];   // [slot][warpInNode][head][dim]
    __shared__ float s_sum[2][4][4];       // [slot][warpInNode][head]

    int t = threadIdx.x;
    int slot = t >> 7;
    int win  = (t >> 5) & 3;
    int lane = t & 31;
    int node = blockIdx.x * 2 + slot;

    unsigned a01[4], a23[4];
    float w2l[4][4], eb2[4];
#pragma unroll
    for (int h = 0; h < 4; h++) {
        uint2 ar = *(const uint2*)(g_A + (size_t)node * 512 + h * 128 + lane * 4);
        a01[h] = ar.x;
        a23[h] = ar.y;
        float4 wv = *(const float4*)&w2[h * 128 + lane * 4];
        w2l[h][0] = wv.x; w2l[h][1] = wv.y; w2l[h][2] = wv.z; w2l[h][3] = wv.w;
        eb2[h] = __expf(b2[h]);
    }

    float acc[4][2];
#pragma unroll
    for (int h = 0; h < 4; h++) { acc[h][0] = 0.f; acc[h][1] = 0.f; }
    float ssum[4] = {0.f, 0.f, 0.f, 0.f};

    int beg = g_off[node], end = g_off[node + 1];
    int len = end - beg;
    int q = len >> 2, rmd = len & 3;
    int myBeg = beg + win * q + min(win, rmd);
    int myEnd = myBeg + q + (win < rmd ? 1 : 0);

    int i = myBeg;
    for (; i + 1 < myEnd; i += 2) {
        int c0 = g_scol[i];
        int c1 = g_scol[i + 1];
        uint2 br0[4], br1[4];
        const __half* bp0 = g_B + (size_t)c0 * 512 + lane * 4;
        const __half* bp1 = g_B + (size_t)c1 * 512 + lane * 4;
#pragma unroll
        for (int h = 0; h < 4; h++) br0[h] = *(const uint2*)(bp0 + h * 128);
#pragma unroll
        for (int h = 0; h < 4; h++) br1[h] = *(const uint2*)(bp1 + h * 128);
        float2 xv0 = *(const float2*)&x[c0 * 64 + lane * 2];
        float2 xv1 = *(const float2*)&x[c1 * 64 + lane * 2];

        float p0[4], p1[4];
#pragma unroll
        for (int h = 0; h < 4; h++) {
            // edge 0: a+b in half2, packed tanh, fp32 dot
            float2 f01 = h2f2(h2tanh(h2add(a01[h], br0[h].x)));
            float2 f23 = h2f2(h2tanh(h2add(a23[h], br0[h].y)));
            float s = 0.f;
            s = fmaf(w2l[h][0], f01.x, s);
            s = fmaf(w2l[h][1], f01.y, s);
            s = fmaf(w2l[h][2], f23.x, s);
            s = fmaf(w2l[h][3], f23.y, s);
            p0[h] = s;
            // edge 1
            float2 g01 = h2f2(h2tanh(h2add(a01[h], br1[h].x)));
            float2 g23 = h2f2(h2tanh(h2add(a23[h], br1[h].y)));
            float u = 0.f;
            u = fmaf(w2l[h][0], g01.x, u);
            u = fmaf(w2l[h][1], g01.y, u);
            u = fmaf(w2l[h][2], g23.x, u);
            u = fmaf(w2l[h][3], g23.y, u);
            p1[h] = u;
        }
#pragma unroll
        for (int o = 16; o; o >>= 1) {
            p0[0] += __shfl_xor_sync(0xffffffffu, p0[0], o);
            p0[1] += __shfl_xor_sync(0xffffffffu, p0[1], o);
            p0[2] += __shfl_xor_sync(0xffffffffu, p0[2], o);
            p0[3] += __shfl_xor_sync(0xffffffffu, p0[3], o);
            p1[0] += __shfl_xor_sync(0xffffffffu, p1[0], o);
            p1[1] += __shfl_xor_sync(0xffffffffu, p1[1], o);
            p1[2] += __shfl_xor_sync(0xffffffffu, p1[2], o);
            p1[3] += __shfl_xor_sync(0xffffffffu, p1[3], o);
        }
#pragma unroll
        for (int h = 0; h < 4; h++) {
            float e0 = __expf(p0[h]) * eb2[h];
            float e1 = __expf(p1[h]) * eb2[h];
            ssum[h] += e0 + e1;
            acc[h][0] = fmaf(e0, xv0.x, acc[h][0]);
            acc[h][1] = fmaf(e0, xv0.y, acc[h][1]);
            acc[h][0] = fmaf(e1, xv1.x, acc[h][0]);
            acc[h][1] = fmaf(e1, xv1.y, acc[h][1]);
        }
    }
    if (i < myEnd) {
        int c = g_scol[i];
        float part[4];
#pragma unroll
        for (int h = 0; h < 4; h++) {
            uint2 br = *(const uint2*)(g_B + (size_t)c * 512 + h * 128 + lane * 4);
            float2 f01 = h2f2(h2tanh(h2add(a01[h], br.x)));
            float2 f23 = h2f2(h2tanh(h2add(a23[h], br.y)));
            float s = 0.f;
            s = fmaf(w2l[h][0], f01.x, s);
            s = fmaf(w2l[h][1], f01.y, s);
            s = fmaf(w2l[h][2], f23.x, s);
            s = fmaf(w2l[h][3], f23.y, s);
            part[h] = s;
        }
#pragma unroll
        for (int o = 16; o; o >>= 1) {
            part[0] += __shfl_xor_sync(0xffffffffu, part[0], o);
            part[1] += __shfl_xor_sync(0xffffffffu, part[1], o);
            part[2] += __shfl_xor_sync(0xffffffffu, part[2], o);
            part[3] += __shfl_xor_sync(0xffffffffu, part[3], o);
        }
        float2 xv = *(const float2*)&x[c * 64 + lane * 2];
#pragma unroll
        for (int h = 0; h < 4; h++) {
            float e = __expf(part[h]) * eb2[h];
            ssum[h] += e;
            acc[h][0] = fmaf(e, xv.x, acc[h][0]);
            acc[h][1] = fmaf(e, xv.y, acc[h][1]);
        }
    }

#pragma unroll
    for (int h = 0; h < 4; h++) {
        *(float2*)&s_acc[slot][win][h][lane * 2] = make_float2(acc[h][0], acc[h][1]);
    }
    if (lane == 0) {
#pragma unroll
        for (int h = 0; h < 4; h++) s_sum[slot][win][h] = ssum[h];
    }
    __syncthreads();

    for (int idx = t; idx < 512; idx += 256) {
        int sl = idx >> 8;
        int rest = idx & 255;
        int h = rest >> 6, d = rest & 63;
        int nn = blockIdx.x * 2 + sl;
        float v = s_acc[sl][0][h][d] + s_acc[sl][1][h][d]
                + s_acc[sl][2][h][d] + s_acc[sl][3][h][d];
        g_agg[(size_t)nn * 256 + h * 64 + d] = v;
    }
    if (t < 8) {
        int sl = t >> 2, h = t & 3;
        float v = s_sum[sl][0][h] + s_sum[sl][1][h] + s_sum[sl][2][h] + s_sum[sl][3][h];
        atomicAdd(&g_S[h], v);
    }
}

// ---------------- node GEMMs via wmma with power-of-2 scaling; L=1 fuses classifier ----
template <int KDIM, int L>
__global__ __launch_bounds__(256) void k_ngemm(
    const float* __restrict__ W, const float* __restrict__ bias,
    const float* __restrict__ bng, const float* __restrict__ bnb,
    const float* __restrict__ bnm, const float* __restrict__ bnv,
    const float* __restrict__ clw, const float* __restrict__ clb,
    float* __restrict__ out)
{
    __shared__ __align__(16) char sm[SMB];
    __half* Xs = (__half*)sm;
    __half* Ws = (__half*)(sm + 128 * XS_LD * 2);
    float*  St = (float*)sm;
    __shared__ float sinv[4];
    __shared__ float Wc[256];

    constexpr float UPSCALE   = (L == 0) ? 65536.f : 262144.f;
    constexpr float DOWNSCALE = 1.f / UPSCALE;

    const float* Ag = (L == 0) ? g_agg : g_h0;
    float* Og = g_h0;

    int t = threadIdx.x;
    int warp = t >> 5;
    int n0 = blockIdx.x * 128;
    if (L == 0) {
        if (t < 4) sinv[t] = UPSCALE / g_S[t];
        __syncthreads();
    } else {
        Wc[t] = clw[t];
        __syncthreads();
    }

    int m0w = (warp >> 1) * 32;
    int n0w = (warp & 1) * 64;

    wmma::fragment<wmma::accumulator, 16, 16, 16, float> acc[2][4];
#pragma unroll
    for (int mi = 0; mi < 2; mi++)
#pragma unroll
        for (int ni = 0; ni < 4; ni++) wmma::fill_fragment(acc[mi][ni], 0.f);

    for (int kc = 0; kc < KDIM; kc += 64) {
        __syncthreads();
#pragma unroll
        for (int i = 0; i < 8; i++) {
            int id = t + i * 256;
            int r = id >> 4;
            int c4 = (id & 15) * 4;
            int n = n0 + r;
            float4 v = make_float4(0.f, 0.f, 0.f, 0.f);
            if (n < N_NODES) v = *(const float4*)(Ag + (size_t)n * KDIM + kc + c4);
            float s = (L == 0) ? sinv[(kc + c4) >> 6] : UPSCALE;
            v.x *= s; v.y *= s; v.z *= s; v.w *= s;
            *(__half2*)(Xs + r * XS_LD + c4)     = __floats2half2_rn(v.x, v.y);
            *(__half2*)(Xs + r * XS_LD + c4 + 2) = __floats2half2_rn(v.z, v.w);
        }
#pragma unroll
        for (int i = 0; i < 8; i++) {
            int id = t + i * 256;
            int kr = id >> 5;
            int d4 = (id & 31) * 4;
            float4 v = *(const float4*)(W + (size_t)(kc + kr) * HID + d4);
            *(__half2*)(Ws + kr * WS_LD + d4)     = __floats2half2_rn(v.x, v.y);
            *(__half2*)(Ws + kr * WS_LD + d4 + 2) = __floats2half2_rn(v.z, v.w);
        }
        __syncthreads();
#pragma unroll
        for (int kk = 0; kk < 4; kk++) {
            wmma::fragment<wmma::matrix_a, 16, 16, 16, __half, wmma::row_major> af[2];
            wmma::fragment<wmma::matrix_b, 16, 16, 16, __half, wmma::row_major> bf[4];
#pragma unroll
            for (int mi = 0; mi < 2; mi++)
                wmma::load_matrix_sync(af[mi], Xs + (m0w + mi * 16) * XS_LD + kk * 16, XS_LD);
#pragma unroll
            for (int ni = 0; ni < 4; ni++)
                wmma::load_matrix_sync(bf[ni], Ws + (kk * 16) * WS_LD + n0w + ni * 16, WS_LD);
#pragma unroll
            for (int mi = 0; mi < 2; mi++)
#pragma unroll
                for (int ni = 0; ni < 4; ni++)
                    wmma::mma_sync(acc[mi][ni], af[mi], bf[ni], acc[mi][ni]);
        }
    }

#pragma unroll
    for (int hh = 0; hh < 2; hh++) {
        __syncthreads();
        if ((warp >> 2) == hh) {
#pragma unroll
            for (int mi = 0; mi < 2; mi++)
#pragma unroll
                for (int ni = 0; ni < 4; ni++)
                    wmma::store_matrix_sync(St + (m0w - hh * 64 + mi * 16) * ST_LD + n0w + ni * 16,
                                            acc[mi][ni], ST_LD, wmma::mem_row_major);
        }
        __syncthreads();
#pragma unroll
        for (int i = 0; i < 16; i++) {
            int id = t + i * 256;
            int r = id >> 6, pc = id & 63;
            int n = n0 + hh * 64 + r;
            if (n >= N_NODES) continue;
            int d = 2 * pc;
            float v0 = St[r * ST_LD + d]     * DOWNSCALE + bias[d];
            float v1 = St[r * ST_LD + d + 1] * DOWNSCALE + bias[d + 1];
            float g0 = bng[L * 128 + d]     * rsqrtf(bnv[L * 128 + d]     + 1e-5f);
            float g1 = bng[L * 128 + d + 1] * rsqrtf(bnv[L * 128 + d + 1] + 1e-5f);
            v0 = (v0 - bnm[L * 128 + d])     * g0 + bnb[L * 128 + d];
            v1 = (v1 - bnm[L * 128 + d + 1]) * g1 + bnb[L * 128 + d + 1];
            v0 = fmaxf(v0, 0.f);
            v1 = fmaxf(v1, 0.f);
            if (L == 0) {
                *(float2*)(Og + (size_t)n * HID + d) = make_float2(v0, v1);
            } else {
                St[r * ST_LD + d]     = v0;
                St[r * ST_LD + d + 1] = v1;
            }
        }
        if (L == 1) {
            __syncthreads();
            int r = t >> 2, qq = t & 3;
            int n = n0 + hh * 64 + r;
            float c0 = 0.f, c1 = 0.f;
            int k0 = qq * 32;
#pragma unroll
            for (int k = 0; k < 32; k++) {
                float v = St[r * ST_LD + k0 + k];
                c0 = fmaf(v, Wc[(k0 + k) * 2], c0);
                c1 = fmaf(v, Wc[(k0 + k) * 2 + 1], c1);
            }
            c0 += __shfl_xor_sync(0xffffffffu, c0, 1);
            c0 += __shfl_xor_sync(0xffffffffu, c0, 2);
            c1 += __shfl_xor_sync(0xffffffffu, c1, 1);
            c1 += __shfl_xor_sync(0xffffffffu, c1, 2);
            if (qq == 0 && n < N_NODES) {
                out[n * 2]     = c0 + clb[0];
                out[n * 2 + 1] = c1 + clb[1];
            }
        }
    }
}

// ---------------- launch ----------------
extern "C" void kernel_launch(void* const* d_in, const int* in_sizes, int n_in,
                              void* d_out, int out_size)
{
    const float* x   = (const float*)d_in[0];
    const void*  ei  = d_in[1];
    const float* w1  = (const float*)d_in[2];
    const float* b1  = (const float*)d_in[3];
    const float* w2  = (const float*)d_in[4];
    const float* b2  = (const float*)d_in[5];
    const float* cw0 = (const float*)d_in[6];
    const float* cb0 = (const float*)d_in[7];
    const float* cw1 = (const float*)d_in[8];
    const float* cb1 = (const float*)d_in[9];
    const float* bng = (const float*)d_in[10];
    const float* bnb = (const float*)d_in[11];
    const float* bnm = (const float*)d_in[12];
    const float* bnv = (const float*)d_in[13];
    const float* clw = (const float*)d_in[14];
    const float* clb = (const float*)d_in[15];
    float*       out = (float*)d_out;

    int nblk128 = (N_NODES + 127) / 128;

    k_zero<<<(N_NODES + 255) / 256, 256>>>();
    k_detect<<<1, 256>>>((const int*)ei);
    k_convert_hist<<<(2 * NE + 255) / 256, 256>>>(ei);

    k_ab_mma<<<dim3(nblk128, 8), 256>>>(x, w1, b1);

    k_scan<<<1, 1024>>>();
    k_scatter<<<(NE + 255) / 256, 256>>>();
    k_edge<<<N_NODES / 2, 256>>>(x, w2, b2);

    k_ngemm<256, 0><<<nblk128, 256>>>(cw0, cb0, bng, bnb, bnm, bnv, nullptr, nullptr, nullptr);
    k_ngemm<128, 1><<<nblk128, 256>>>(cw1, cb1, bng, bnb, bnm, bnv, clw, clb, out);
}

// round 16
// speedup vs baseline: 1.3854x; 1.0639x over previous
#include <cuda_runtime.h>
#include <cuda_fp16.h>
#include <cstdint>
#include <mma.h>
using namespace nvcuda;

// Problem constants (fixed by the dataset)
#define N_NODES 50000
#define NE      800000
#define IN_DIM  64
#define HID     128
#define HEADS   4
#define NCLS    2

// ---------------- scratch: EXACT layout of the passing Round-9..15 kernel ----------------
__device__ __half g_A[N_NODES * HEADS * HID];   // 51.2MB
__device__ __half g_B[N_NODES * HEADS * HID];   // 51.2MB
__device__ float  g_agg[N_NODES * HEADS * IN_DIM]; // 51.2MB
__device__ float  g_h0[N_NODES * HID];          // 25.6MB
__device__ float  g_h1[N_NODES * HID];          // 25.6MB (unused; kept for layout pedigree)
__device__ int    g_cnt[N_NODES];
__device__ int    g_off[N_NODES + 1];
__device__ int    g_cur[N_NODES];
__device__ int    g_scol[NE];
__device__ int    g_ei32[2 * NE];
__device__ float  g_S[HEADS];
__device__ int    g_is64;

__device__ __forceinline__ unsigned h2tanh(unsigned v) {
    unsigned r;
    asm("tanh.approx.f16x2 %0, %1;" : "=r"(r) : "r"(v));
    return r;
}

__device__ __forceinline__ unsigned h2add(unsigned a, unsigned b) {
    __half2 r = __hadd2(*(__half2*)&a, *(__half2*)&b);
    return *(unsigned*)&r;
}

__device__ __forceinline__ float2 h2f2(unsigned v) {
    return __half22float2(*(__half2*)&v);
}

// ---------------- K0a: detect edge_index dtype (int64 vs int32) ----------------
__global__ void k_detect(const int* __restrict__ ei32) {
    __shared__ int any;
    if (threadIdx.x == 0) any = 0;
    __syncthreads();
    for (int i = threadIdx.x; i < 1024; i += blockDim.x) {
        if (ei32[2 * i + 1] != 0) any = 1;
    }
    __syncthreads();
    if (threadIdx.x == 0) g_is64 = (any == 0) ? 1 : 0;
}

// ---------------- convert + histogram fused ----------------
__global__ void k_convert_hist(const void* __restrict__ ei) {
    int e = blockIdx.x * blockDim.x + threadIdx.x;
    if (e < 2 * NE) {
        int v;
        if (g_is64) v = (int)((const long long*)ei)[e];
        else        v = ((const int*)ei)[e];
        g_ei32[e] = v;
        if (e < NE) atomicAdd(&g_cnt[v], 1);
    }
}

__global__ void k_zero() {
    int i = blockIdx.x * blockDim.x + threadIdx.x;
    if (i < N_NODES) g_cnt[i] = 0;
    if (i < HEADS) g_S[i] = 0.f;
}

// ---------------- K1: A/B tables via wmma (unchanged) ----------------
#define XS_LD 72
#define WS_LD 136
#define ST_LD 132
#define SMB   (128 * XS_LD * 2 + 64 * WS_LD * 2)   // 35840 bytes

__global__ __launch_bounds__(256) void k_ab_mma(
    const float* __restrict__ x, const float* __restrict__ w1, const float* __restrict__ b1)
{
    __shared__ __align__(16) char sm[SMB];
    __half* Xs = (__half*)sm;
    __half* Ws = (__half*)(sm + 128 * XS_LD * 2);
    float*  St = (float*)sm;

    int t = threadIdx.x;
    int warp = t >> 5;
    int n0 = blockIdx.x * 128;
    int part = blockIdx.y;
    int head = part & 3;
    bool isA = part < 4;
    int krow0 = isA ? 0 : IN_DIM;

#pragma unroll
    for (int i = 0; i < 8; i++) {
        int id = t + i * 256;
        int r = id >> 4;
        int c4 = (id & 15) * 4;
        int n = n0 + r;
        float4 v = make_float4(0.f, 0.f, 0.f, 0.f);
        if (n < N_NODES) v = *(const float4*)(x + (size_t)n * IN_DIM + c4);
        *(__half2*)(Xs + r * XS_LD + c4)     = __floats2half2_rn(v.x, v.y);
        *(__half2*)(Xs + r * XS_LD + c4 + 2) = __floats2half2_rn(v.z, v.w);
    }
#pragma unroll
    for (int i = 0; i < 8; i++) {
        int id = t + i * 256;
        int kr = id >> 5;
        int d4 = (id & 31) * 4;
        float4 v = *(const float4*)(w1 + head * (2 * IN_DIM * HID) + (size_t)(krow0 + kr) * HID + d4);
        *(__half2*)(Ws + kr * WS_LD + d4)     = __floats2half2_rn(v.x, v.y);
        *(__half2*)(Ws + kr * WS_LD + d4 + 2) = __floats2half2_rn(v.z, v.w);
    }
    __syncthreads();

    int m0w = (warp >> 1) * 32;
    int n0w = (warp & 1) * 64;

    wmma::fragment<wmma::accumulator, 16, 16, 16, float> acc[2][4];
#pragma unroll
    for (int mi = 0; mi < 2; mi++)
#pragma unroll
        for (int ni = 0; ni < 4; ni++) wmma::fill_fragment(acc[mi][ni], 0.f);

#pragma unroll
    for (int kk = 0; kk < 4; kk++) {
        wmma::fragment<wmma::matrix_a, 16, 16, 16, __half, wmma::row_major> af[2];
        wmma::fragment<wmma::matrix_b, 16, 16, 16, __half, wmma::row_major> bf[4];
#pragma unroll
        for (int mi = 0; mi < 2; mi++)
            wmma::load_matrix_sync(af[mi], Xs + (m0w + mi * 16) * XS_LD + kk * 16, XS_LD);
#pragma unroll
        for (int ni = 0; ni < 4; ni++)
            wmma::load_matrix_sync(bf[ni], Ws + (kk * 16) * WS_LD + n0w + ni * 16, WS_LD);
#pragma unroll
        for (int mi = 0; mi < 2; mi++)
#pragma unroll
            for (int ni = 0; ni < 4; ni++)
                wmma::mma_sync(acc[mi][ni], af[mi], bf[ni], acc[mi][ni]);
    }

    __half* dst = isA ? g_A : g_B;
#pragma unroll
    for (int hh = 0; hh < 2; hh++) {
        __syncthreads();
        if ((warp >> 2) == hh) {
#pragma unroll
            for (int mi = 0; mi < 2; mi++)
#pragma unroll
                for (int ni = 0; ni < 4; ni++)
                    wmma::store_matrix_sync(St + (m0w - hh * 64 + mi * 16) * ST_LD + n0w + ni * 16,
                                            acc[mi][ni], ST_LD, wmma::mem_row_major);
        }
        __syncthreads();
#pragma unroll
        for (int i = 0; i < 16; i++) {
            int id = t + i * 256;
            int r = id >> 6, pc = id & 63;
            int n = n0 + hh * 64 + r;
            if (n >= N_NODES) continue;
            int d = 2 * pc;
            float v0 = St[r * ST_LD + d];
            float v1 = St[r * ST_LD + d + 1];
            if (isA) {
                v0 += b1[head * HID + d];
                v1 += b1[head * HID + d + 1];
            }
            *(__half2*)(dst + (size_t)n * (HEADS * HID) + head * HID + d) = __floats2half2_rn(v0, v1);
        }
    }
}

// ---------------- scan (verbatim) ----------------
__global__ __launch_bounds__(1024) void k_scan() {
    __shared__ int wsum[32];
    __shared__ int carry;
    int t = threadIdx.x, lane = t & 31, wid = t >> 5;
    if (t == 0) carry = 0;
    __syncthreads();
    for (int base = 0; base < N_NODES; base += 1024) {
        int i = base + t;
        int v = (i < N_NODES) ? g_cnt[i] : 0;
        int s = v;
#pragma unroll
        for (int o = 1; o < 32; o <<= 1) {
            int u = __shfl_up_sync(0xffffffffu, s, o);
            if (lane >= o) s += u;
        }
        if (lane == 31) wsum[wid] = s;
        __syncthreads();
        if (wid == 0) {
            int ws = wsum[lane];
#pragma unroll
            for (int o = 1; o < 32; o <<= 1) {
                int u = __shfl_up_sync(0xffffffffu, ws, o);
                if (lane >= o) ws += u;
            }
            wsum[lane] = ws;
        }
        __syncthreads();
        int incl = s + ((wid > 0) ? wsum[wid - 1] : 0) + carry;
        if (i < N_NODES) {
            int ex = incl - v;
            g_off[i] = ex;
            g_cur[i] = ex;
        }
        __syncthreads();
        if (t == 1023) carry = incl;
        __syncthreads();
    }
    if (t == 0) g_off[N_NODES] = carry;
}

__global__ void k_scatter() {
    int e = blockIdx.x * blockDim.x + threadIdx.x;
    if (e < NE) {
        int r = g_ei32[e];
        int c = g_ei32[NE + e];
        int p = atomicAdd(&g_cur[r], 1);
        g_scol[p] = c;
    }
}

// ---------------- fused edge pass: 4 warps per node, 2 nodes per block ----------------
// Head-per-lane-group layout: lane = (g = lane>>3 head, j = lane&7 dim-block).
// Each lane owns 16 contiguous dims of one head -> 3-round 8-lane reduction,
// 1 exp per lane-edge, per-head weights broadcast via 4 shfl.
__global__ __launch_bounds__(256) void k_edge(
    const float* __restrict__ x, const float* __restrict__ w2, const float* __restrict__ b2)
{
    __shared__ float s_acc[2][4][4][64];   // [slot][warpInNode][head][dim]
    __shared__ float s_sum[2][4][4];       // [slot][warpInNode][head]

    int t = threadIdx.x;
    int slot = t >> 7;
    int win  = (t >> 5) & 3;
    int lane = t & 31;
    int g = lane >> 3;       // head
    int j = lane & 7;        // dim block (16 dims)
    int node = blockIdx.x * 2 + slot;

    // A segment: head g, dims [j*16, j*16+16)
    uint4 a0 = *(const uint4*)(g_A + (size_t)node * 512 + g * 128 + j * 16);
    uint4 a1 = *(const uint4*)(g_A + (size_t)node * 512 + g * 128 + j * 16 + 8);
    const unsigned* pa0 = (const unsigned*)&a0;
    const unsigned* pa1 = (const unsigned*)&a1;

    float w[16];
#pragma unroll
    for (int k = 0; k < 4; k++) {
        float4 wv = *(const float4*)&w2[g * 128 + j * 16 + k * 4];
        w[k * 4 + 0] = wv.x; w[k * 4 + 1] = wv.y; w[k * 4 + 2] = wv.z; w[k * 4 + 3] = wv.w;
    }
    float eb2g = __expf(b2[g]);

    float acc[4][2];
#pragma unroll
    for (int h = 0; h < 4; h++) { acc[h][0] = 0.f; acc[h][1] = 0.f; }
    float ssum = 0.f;

    int beg = g_off[node], end = g_off[node + 1];
    int len = end - beg;
    int q = len >> 2, rmd = len & 3;
    int myBeg = beg + win * q + min(win, rmd);
    int myEnd = myBeg + q + (win < rmd ? 1 : 0);

    int i = myBeg;
    for (; i + 1 < myEnd; i += 2) {
        int c0 = g_scol[i];
        int c1 = g_scol[i + 1];
        uint4 b00 = *(const uint4*)(g_B + (size_t)c0 * 512 + g * 128 + j * 16);
        uint4 b01 = *(const uint4*)(g_B + (size_t)c0 * 512 + g * 128 + j * 16 + 8);
        uint4 b10 = *(const uint4*)(g_B + (size_t)c1 * 512 + g * 128 + j * 16);
        uint4 b11 = *(const uint4*)(g_B + (size_t)c1 * 512 + g * 128 + j * 16 + 8);
        float2 xv0 = *(const float2*)&x[c0 * 64 + lane * 2];
        float2 xv1 = *(const float2*)&x[c1 * 64 + lane * 2];

        const unsigned* pb00 = (const unsigned*)&b00;
        const unsigned* pb01 = (const unsigned*)&b01;
        const unsigned* pb10 = (const unsigned*)&b10;
        const unsigned* pb11 = (const unsigned*)&b11;

        float p0 = 0.f, p1 = 0.f;
#pragma unroll
        for (int k = 0; k < 4; k++) {
            float2 f = h2f2(h2tanh(h2add(pa0[k], pb00[k])));
            p0 = fmaf(w[2 * k], f.x, p0);
            p0 = fmaf(w[2 * k + 1], f.y, p0);
            float2 f2 = h2f2(h2tanh(h2add(pa1[k], pb01[k])));
            p0 = fmaf(w[8 + 2 * k], f2.x, p0);
            p0 = fmaf(w[8 + 2 * k + 1], f2.y, p0);
            float2 u = h2f2(h2tanh(h2add(pa0[k], pb10[k])));
            p1 = fmaf(w[2 * k], u.x, p1);
            p1 = fmaf(w[2 * k + 1], u.y, p1);
            float2 u2 = h2f2(h2tanh(h2add(pa1[k], pb11[k])));
            p1 = fmaf(w[8 + 2 * k], u2.x, p1);
            p1 = fmaf(w[8 + 2 * k + 1], u2.y, p1);
        }
        // reduce within 8-lane head group
        p0 += __shfl_xor_sync(0xffffffffu, p0, 4);
        p1 += __shfl_xor_sync(0xffffffffu, p1, 4);
        p0 += __shfl_xor_sync(0xffffffffu, p0, 2);
        p1 += __shfl_xor_sync(0xffffffffu, p1, 2);
        p0 += __shfl_xor_sync(0xffffffffu, p0, 1);
        p1 += __shfl_xor_sync(0xffffffffu, p1, 1);

        float e0 = __expf(p0) * eb2g;
        float e1 = __expf(p1) * eb2g;
        ssum += e0 + e1;
#pragma unroll
        for (int h = 0; h < 4; h++) {
            float eh0 = __shfl_sync(0xffffffffu, e0, h << 3);
            float eh1 = __shfl_sync(0xffffffffu, e1, h << 3);
            acc[h][0] = fmaf(eh0, xv0.x, acc[h][0]);
            acc[h][1] = fmaf(eh0, xv0.y, acc[h][1]);
            acc[h][0] = fmaf(eh1, xv1.x, acc[h][0]);
            acc[h][1] = fmaf(eh1, xv1.y, acc[h][1]);
        }
    }
    if (i < myEnd) {
        int c = g_scol[i];
        uint4 b0 = *(const uint4*)(g_B + (size_t)c * 512 + g * 128 + j * 16);
        uint4 b1v = *(const uint4*)(g_B + (size_t)c * 512 + g * 128 + j * 16 + 8);
        float2 xv = *(const float2*)&x[c * 64 + lane * 2];
        const unsigned* pb0 = (const unsigned*)&b0;
        const unsigned* pb1 = (const unsigned*)&b1v;

        float p = 0.f;
#pragma unroll
        for (int k = 0; k < 4; k++) {
            float2 f = h2f2(h2tanh(h2add(pa0[k], pb0[k])));
            p = fmaf(w[2 * k], f.x, p);
            p = fmaf(w[2 * k + 1], f.y, p);
            float2 f2 = h2f2(h2tanh(h2add(pa1[k], pb1[k])));
            p = fmaf(w[8 + 2 * k], f2.x, p);
            p = fmaf(w[8 + 2 * k + 1], f2.y, p);
        }
        p += __shfl_xor_sync(0xffffffffu, p, 4);
        p += __shfl_xor_sync(0xffffffffu, p, 2);
        p += __shfl_xor_sync(0xffffffffu, p, 1);

        float e = __expf(p) * eb2g;
        ssum += e;
#pragma unroll
        for (int h = 0; h < 4; h++) {
            float eh = __shfl_sync(0xffffffffu, e, h << 3);
            acc[h][0] = fmaf(eh, xv.x, acc[h][0]);
            acc[h][1] = fmaf(eh, xv.y, acc[h][1]);
        }
    }

#pragma unroll
    for (int h = 0; h < 4; h++) {
        *(float2*)&s_acc[slot][win][h][lane * 2] = make_float2(acc[h][0], acc[h][1]);
    }
    if (j == 0) s_sum[slot][win][g] = ssum;
    __syncthreads();

    for (int idx = t; idx < 512; idx += 256) {
        int sl = idx >> 8;
        int rest = idx & 255;
        int h = rest >> 6, d = rest & 63;
        int nn = blockIdx.x * 2 + sl;
        float v = s_acc[sl][0][h][d] + s_acc[sl][1][h][d]
                + s_acc[sl][2][h][d] + s_acc[sl][3][h][d];
        g_agg[(size_t)nn * 256 + h * 64 + d] = v;
    }
    if (t < 8) {
        int sl = t >> 2, h = t & 3;
        float v = s_sum[sl][0][h] + s_sum[sl][1][h] + s_sum[sl][2][h] + s_sum[sl][3][h];
        atomicAdd(&g_S[h], v);
    }
}

// ---------------- node GEMMs via wmma with power-of-2 scaling; L=1 fuses classifier ----
template <int KDIM, int L>
__global__ __launch_bounds__(256) void k_ngemm(
    const float* __restrict__ W, const float* __restrict__ bias,
    const float* __restrict__ bng, const float* __restrict__ bnb,
    const float* __restrict__ bnm, const float* __restrict__ bnv,
    const float* __restrict__ clw, const float* __restrict__ clb,
    float* __restrict__ out)
{
    __shared__ __align__(16) char sm[SMB];
    __half* Xs = (__half*)sm;
    __half* Ws = (__half*)(sm + 128 * XS_LD * 2);
    float*  St = (float*)sm;
    __shared__ float sinv[4];
    __shared__ float Wc[256];

    constexpr float UPSCALE   = (L == 0) ? 65536.f : 262144.f;
    constexpr float DOWNSCALE = 1.f / UPSCALE;

    const float* Ag = (L == 0) ? g_agg : g_h0;
    float* Og = g_h0;

    int t = threadIdx.x;
    int warp = t >> 5;
    int n0 = blockIdx.x * 128;
    if (L == 0) {
        if (t < 4) sinv[t] = UPSCALE / g_S[t];
        __syncthreads();
    } else {
        Wc[t] = clw[t];
        __syncthreads();
    }

    int m0w = (warp >> 1) * 32;
    int n0w = (warp & 1) * 64;

    wmma::fragment<wmma::accumulator, 16, 16, 16, float> acc[2][4];
#pragma unroll
    for (int mi = 0; mi < 2; mi++)
#pragma unroll
        for (int ni = 0; ni < 4; ni++) wmma::fill_fragment(acc[mi][ni], 0.f);

    for (int kc = 0; kc < KDIM; kc += 64) {
        __syncthreads();
#pragma unroll
        for (int i = 0; i < 8; i++) {
            int id = t + i * 256;
            int r = id >> 4;
            int c4 = (id & 15) * 4;
            int n = n0 + r;
            float4 v = make_float4(0.f, 0.f, 0.f, 0.f);
            if (n < N_NODES) v = *(const float4*)(Ag + (size_t)n * KDIM + kc + c4);
            float s = (L == 0) ? sinv[(kc + c4) >> 6] : UPSCALE;
            v.x *= s; v.y *= s; v.z *= s; v.w *= s;
            *(__half2*)(Xs + r * XS_LD + c4)     = __floats2half2_rn(v.x, v.y);
            *(__half2*)(Xs + r * XS_LD + c4 + 2) = __floats2half2_rn(v.z, v.w);
        }
#pragma unroll
        for (int i = 0; i < 8; i++) {
            int id = t + i * 256;
            int kr = id >> 5;
            int d4 = (id & 31) * 4;
            float4 v = *(const float4*)(W + (size_t)(kc + kr) * HID + d4);
            *(__half2*)(Ws + kr * WS_LD + d4)     = __floats2half2_rn(v.x, v.y);
            *(__half2*)(Ws + kr * WS_LD + d4 + 2) = __floats2half2_rn(v.z, v.w);
        }
        __syncthreads();
#pragma unroll
        for (int kk = 0; kk < 4; kk++) {
            wmma::fragment<wmma::matrix_a, 16, 16, 16, __half, wmma::row_major> af[2];
            wmma::fragment<wmma::matrix_b, 16, 16, 16, __half, wmma::row_major> bf[4];
#pragma unroll
            for (int mi = 0; mi < 2; mi++)
                wmma::load_matrix_sync(af[mi], Xs + (m0w + mi * 16) * XS_LD + kk * 16, XS_LD);
#pragma unroll
            for (int ni = 0; ni < 4; ni++)
                wmma::load_matrix_sync(bf[ni], Ws + (kk * 16) * WS_LD + n0w + ni * 16, WS_LD);
#pragma unroll
            for (int mi = 0; mi < 2; mi++)
#pragma unroll
                for (int ni = 0; ni < 4; ni++)
                    wmma::mma_sync(acc[mi][ni], af[mi], bf[ni], acc[mi][ni]);
        }
    }

#pragma unroll
    for (int hh = 0; hh < 2; hh++) {
        __syncthreads();
        if ((warp >> 2) == hh) {
#pragma unroll
            for (int mi = 0; mi < 2; mi++)
#pragma unroll
                for (int ni = 0; ni < 4; ni++)
                    wmma::store_matrix_sync(St + (m0w - hh * 64 + mi * 16) * ST_LD + n0w + ni * 16,
                                            acc[mi][ni], ST_LD, wmma::mem_row_major);
        }
        __syncthreads();
#pragma unroll
        for (int i = 0; i < 16; i++) {
            int id = t + i * 256;
            int r = id >> 6, pc = id & 63;
            int n = n0 + hh * 64 + r;
            if (n >= N_NODES) continue;
            int d = 2 * pc;
            float v0 = St[r * ST_LD + d]     * DOWNSCALE + bias[d];
            float v1 = St[r * ST_LD + d + 1] * DOWNSCALE + bias[d + 1];
            float g0 = bng[L * 128 + d]     * rsqrtf(bnv[L * 128 + d]     + 1e-5f);
            float g1 = bng[L * 128 + d + 1] * rsqrtf(bnv[L * 128 + d + 1] + 1e-5f);
            v0 = (v0 - bnm[L * 128 + d])     * g0 + bnb[L * 128 + d];
            v1 = (v1 - bnm[L * 128 + d + 1]) * g1 + bnb[L * 128 + d + 1];
            v0 = fmaxf(v0, 0.f);
            v1 = fmaxf(v1, 0.f);
            if (L == 0) {
                *(float2*)(Og + (size_t)n * HID + d) = make_float2(v0, v1);
            } else {
                St[r * ST_LD + d]     = v0;
                St[r * ST_LD + d + 1] = v1;
            }
        }
        if (L == 1) {
            __syncthreads();
            int r = t >> 2, qq = t & 3;
            int n = n0 + hh * 64 + r;
            float c0 = 0.f, c1 = 0.f;
            int k0 = qq * 32;
#pragma unroll
            for (int k = 0; k < 32; k++) {
                float v = St[r * ST_LD + k0 + k];
                c0 = fmaf(v, Wc[(k0 + k) * 2], c0);
                c1 = fmaf(v, Wc[(k0 + k) * 2 + 1], c1);
            }
            c0 += __shfl_xor_sync(0xffffffffu, c0, 1);
            c0 += __shfl_xor_sync(0xffffffffu, c0, 2);
            c1 += __shfl_xor_sync(0xffffffffu, c1, 1);
            c1 += __shfl_xor_sync(0xffffffffu, c1, 2);
            if (qq == 0 && n < N_NODES) {
                out[n * 2]     = c0 + clb[0];
                out[n * 2 + 1] = c1 + clb[1];
            }
        }
    }
}

// ---------------- launch ----------------
extern "C" void kernel_launch(void* const* d_in, const int* in_sizes, int n_in,
                              void* d_out, int out_size)
{
    const float* x   = (const float*)d_in[0];
    const void*  ei  = d_in[1];
    const float* w1  = (const float*)d_in[2];
    const float* b1  = (const float*)d_in[3];
    const float* w2  = (const float*)d_in[4];
    const float* b2  = (const float*)d_in[5];
    const float* cw0 = (const float*)d_in[6];
    const float* cb0 = (const float*)d_in[7];
    const float* cw1 = (const float*)d_in[8];
    const float* cb1 = (const float*)d_in[9];
    const float* bng = (const float*)d_in[10];
    const float* bnb = (const float*)d_in[11];
    const float* bnm = (const float*)d_in[12];
    const float* bnv = (const float*)d_in[13];
    const float* clw = (const float*)d_in[14];
    const float* clb = (const float*)d_in[15];
    float*       out = (float*)d_out;

    int nblk128 = (N_NODES + 127) / 128;

    k_zero<<<(N_NODES + 255) / 256, 256>>>();
    k_detect<<<1, 256>>>((const int*)ei);
    k_convert_hist<<<(2 * NE + 255) / 256, 256>>>(ei);

    k_ab_mma<<<dim3(nblk128, 8), 256>>>(x, w1, b1);

    k_scan<<<1, 1024>>>();
    k_scatter<<<(NE + 255) / 256, 256>>>();
    k_edge<<<N_NODES / 2, 256>>>(x, w2, b2);

    k_ngemm<256, 0><<<nblk128, 256>>>(cw0, cb0, bng, bnb, bnm, bnv, nullptr, nullptr, nullptr);
    k_ngemm<128, 1><<<nblk128, 256>>>(cw1, cb1, bng, bnb, bnm, bnv, clw, clb, out);
}